// round 10
// baseline (speedup 1.0000x reference)
#include <cuda_runtime.h>
#include <cstdint>

#define NN 100000
#define NE_MAX 3200000
#define T_LEN 128
#define OUT_CH 5
#define KW 7
#define L_OUT 41
#define FLAT 205
#define EMB 32
#define HID 16

#define SCAN_BLK 256
#define SCAN_ITEMS 4
#define SCAN_CHUNK (SCAN_BLK * SCAN_ITEMS)          // 1024
#define NBLK ((NN + SCAN_CHUNK - 1) / SCAN_CHUNK)   // 98
#define NTP 20                                      // t-pairs (t=0..39), t=40 tail

// ---- device scratch ----
__device__ __align__(16) float g_p1[NN * HID];
__device__ __align__(16) float g_p2[NN * HID];
__device__ __align__(16) float g_Wc[FLAT * HID];
__device__ __align__(16) float2 g_Wcp[OUT_CH * NTP * HID]; // t-paired folded weight
__device__ __align__(16) float g_Wl[OUT_CH * HID];         // t=40 slice
__device__ float g_bfc[HID];
__device__ float g_wout[HID];
__device__ float g_bout;

// CSR sort scratch
__device__ int g_deg[NN];
__device__ int g_off[NN + 1];
__device__ int g_cur[NN];
__device__ int g_blksum[NBLK];
__device__ int g_sorted[NE_MAX];

// ---- f32x2 helpers ----
__device__ __forceinline__ void fma2(unsigned long long& d, unsigned long long a, unsigned long long b) {
    asm("fma.rn.f32x2 %0, %1, %2, %0;" : "+l"(d) : "l"(a), "l"(b));
}
__device__ __forceinline__ unsigned long long packf2(float lo, float hi) {
    unsigned long long r; asm("mov.b64 %0, {%1, %2};" : "=l"(r) : "f"(lo), "f"(hi)); return r;
}
__device__ __forceinline__ void unpackf2(unsigned long long a, float& lo, float& hi) {
    asm("mov.b64 {%0, %1}, %2;" : "=f"(lo), "=f"(hi) : "l"(a));
}

// ============================================================
// Setup: fold fc->g1w1, build t-paired layout, fold g2w2->ro.
// ============================================================
__global__ void k_setup(const float* __restrict__ fc_w, const float* __restrict__ fc_b,
                        const float* __restrict__ g1w1,
                        const float* __restrict__ g2w2, const float* __restrict__ g2b2,
                        const float* __restrict__ ro_w, const float* __restrict__ ro_b) {
    int tid = threadIdx.x;
    for (int idx = tid; idx < FLAT * HID; idx += blockDim.x) {
        int i = idx >> 4, j = idx & 15;
        float s = 0.f;
        #pragma unroll
        for (int k = 0; k < EMB; k++) s = fmaf(g1w1[j * EMB + k], fc_w[k * FLAT + i], s);
        g_Wc[idx] = s;
    }
    if (tid < HID) {
        float s = 0.f;
        #pragma unroll
        for (int k = 0; k < EMB; k++) s = fmaf(g1w1[tid * EMB + k], fc_b[k], s);
        g_bfc[tid] = s;
        float w = 0.f;
        #pragma unroll
        for (int k = 0; k < HID; k++) w = fmaf(ro_w[k], g2w2[k * HID + tid], w);
        g_wout[tid] = w;
    }
    if (tid == 0) {
        float b = ro_b[0];
        #pragma unroll
        for (int k = 0; k < HID; k++) b = fmaf(ro_w[k], g2b2[k], b);
        g_bout = b;
    }
    __syncthreads();
    // pack: g_Wcp[(c*NTP+tp)*16+j] = { Wc[(c*41+2tp)*16+j], Wc[(c*41+2tp+1)*16+j] }
    for (int idx = tid; idx < OUT_CH * NTP * HID; idx += blockDim.x) {
        int j = idx & 15;
        int tp = (idx >> 4) % NTP;
        int c = idx / (NTP * HID);
        g_Wcp[idx] = make_float2(g_Wc[(c * L_OUT + 2 * tp) * HID + j],
                                 g_Wc[(c * L_OUT + 2 * tp + 1) * HID + j]);
    }
    for (int idx = tid; idx < OUT_CH * HID; idx += blockDim.x) {
        int c = idx >> 4, j = idx & 15;
        g_Wl[idx] = g_Wc[(c * L_OUT + 40) * HID + j];
    }
}

// ============================================================
// CSR build
// ============================================================
__global__ void k_zero() {
    int i = blockIdx.x * 256 + threadIdx.x;
    if (i < NN) g_deg[i] = 0;
}

__global__ void k_hist(const int* __restrict__ ei, int nE) {
    int e = blockIdx.x * 256 + threadIdx.x;
    if (e < nE) atomicAdd(&g_deg[__ldg(&ei[(size_t)nE + e])], 1);
}

// block sums via shfl reduction
__global__ void k_scan1() {
    __shared__ int swp[8];
    int t = threadIdx.x, b = blockIdx.x;
    int lane = t & 31, w = t >> 5;
    int base = b * SCAN_CHUNK + t * SCAN_ITEMS;
    int s = 0;
    #pragma unroll
    for (int i = 0; i < SCAN_ITEMS; i++) {
        int idx = base + i;
        if (idx < NN) s += g_deg[idx];
    }
    #pragma unroll
    for (int off = 16; off > 0; off >>= 1) s += __shfl_xor_sync(0xffffffffu, s, off);
    if (lane == 0) swp[w] = s;
    __syncthreads();
    if (t < 8) {
        int v = swp[t];
        #pragma unroll
        for (int off = 4; off > 0; off >>= 1) v += __shfl_xor_sync(0xffu, v, off);
        if (t == 0) g_blksum[b] = v;
    }
}

// exclusive scan of 98 block sums (1 block, 128 thr)
__global__ void k_scan2() {
    __shared__ int swp[4];
    int t = threadIdx.x, lane = t & 31, w = t >> 5;
    int v = (t < NBLK) ? g_blksum[t] : 0;
    int incl = v;
    #pragma unroll
    for (int off = 1; off < 32; off <<= 1) {
        int u = __shfl_up_sync(0xffffffffu, incl, off);
        if (lane >= off) incl += u;
    }
    if (lane == 31) swp[w] = incl;
    __syncthreads();
    int basew = 0;
    for (int i = 0; i < w; i++) basew += swp[i];
    incl += basew;
    if (t < NBLK) g_blksum[t] = incl - v;
    if (t == 127) g_off[NN] = incl;
}

__global__ void k_scan3() {
    __shared__ int swp[8];
    int t = threadIdx.x, b = blockIdx.x;
    int lane = t & 31, w = t >> 5;
    int base = b * SCAN_CHUNK + t * SCAN_ITEMS;
    int d[SCAN_ITEMS]; int s = 0;
    #pragma unroll
    for (int i = 0; i < SCAN_ITEMS; i++) {
        int idx = base + i;
        d[i] = (idx < NN) ? g_deg[idx] : 0;
        s += d[i];
    }
    int incl = s;
    #pragma unroll
    for (int off = 1; off < 32; off <<= 1) {
        int u = __shfl_up_sync(0xffffffffu, incl, off);
        if (lane >= off) incl += u;
    }
    if (lane == 31) swp[w] = incl;
    __syncthreads();
    int basew = g_blksum[b];
    for (int i = 0; i < w; i++) basew += swp[i];
    int excl = basew + incl - s;
    #pragma unroll
    for (int i = 0; i < SCAN_ITEMS; i++) {
        int idx = base + i;
        if (idx < NN) {
            g_off[idx] = excl;
            g_cur[idx] = excl;
            excl += d[i];
        }
    }
}

__global__ void k_reorder(const int* __restrict__ ei, int nE) {
    int e = blockIdx.x * 256 + threadIdx.x;
    if (e >= nE) return;
    int dst = __ldg(&ei[(size_t)nE + e]);
    int pos = atomicAdd(&g_cur[dst], 1);
    g_sorted[pos] = __ldg(&ei[e]);
}

// ============================================================
// Temporal: conv1d(+ReLU) + folded 205->16 matmul, f32x2 t-pairs
// ============================================================
__global__ __launch_bounds__(128) void k_temporal(const float* __restrict__ x,
                                                  const float* __restrict__ conv_w,
                                                  const float* __restrict__ conv_b,
                                                  int n) {
    __shared__ __align__(16) float2 sWp[OUT_CH * NTP * HID];
    __shared__ __align__(16) float sWl[OUT_CH * HID];
    __shared__ float scw[OUT_CH * KW];
    __shared__ float scb[OUT_CH];
    __shared__ float sbf[HID];
    int tid = threadIdx.x;
    for (int i = tid; i < OUT_CH * NTP * HID; i += 128) sWp[i] = g_Wcp[i];
    for (int i = tid; i < OUT_CH * HID; i += 128) sWl[i] = g_Wl[i];
    if (tid < OUT_CH * KW) scw[tid] = conv_w[tid];
    if (tid < OUT_CH) scb[tid] = conv_b[tid];
    if (tid < HID) sbf[tid] = g_bfc[tid];
    __syncthreads();

    int v = blockIdx.x * 128 + tid;
    if (v >= n) return;

    const float4* x4 = (const float4*)(x + (size_t)v * T_LEN);
    unsigned long long acc2[HID];
    #pragma unroll
    for (int j = 0; j < HID; j++) acc2[j] = packf2(sbf[j], 0.f);

    float f[20];
    #pragma unroll
    for (int q = 0; q < 5; q++) {
        float4 t4 = __ldg(&x4[q]);
        f[q * 4] = t4.x; f[q * 4 + 1] = t4.y; f[q * 4 + 2] = t4.z; f[q * 4 + 3] = t4.w;
    }

    for (int g = 0; g < 10; g++) {          // covers t = 4g..4g+3 (2 t-pairs)
        #pragma unroll
        for (int tph = 0; tph < 2; tph++) {
            int tp = 2 * g + tph;
            // conv for t0 = 4g+2tph (window f[6tph..]) and t1 = t0+1 (f[6tph+3..])
            unsigned long long cvp[OUT_CH];
            #pragma unroll
            for (int c = 0; c < OUT_CH; c++) {
                float s0 = scb[c], s1 = scb[c];
                #pragma unroll
                for (int k = 0; k < KW; k++) {
                    float wk = scw[c * KW + k];
                    s0 = fmaf(wk, f[6 * tph + k], s0);
                    s1 = fmaf(wk, f[6 * tph + 3 + k], s1);
                }
                cvp[c] = packf2(fmaxf(s0, 0.f), fmaxf(s1, 0.f));
            }
            #pragma unroll
            for (int c = 0; c < OUT_CH; c++) {
                const ulonglong2* wp = (const ulonglong2*)&sWp[(c * NTP + tp) * HID];
                #pragma unroll
                for (int i = 0; i < 8; i++) {
                    ulonglong2 w2 = wp[i];
                    fma2(acc2[2 * i + 0], w2.x, cvp[c]);
                    fma2(acc2[2 * i + 1], w2.y, cvp[c]);
                }
            }
        }
        if (g != 9) {
            #pragma unroll
            for (int i = 0; i < 8; i++) f[i] = f[i + 12];
            #pragma unroll
            for (int q = 0; q < 3; q++) {
                float4 t4 = __ldg(&x4[3 * g + 5 + q]);
                f[8 + q * 4] = t4.x; f[9 + q * 4] = t4.y; f[10 + q * 4] = t4.z; f[11 + q * 4] = t4.w;
            }
        }
    }

    // fold pair halves
    float acc[HID];
    #pragma unroll
    for (int j = 0; j < HID; j++) {
        float lo, hi; unpackf2(acc2[j], lo, hi);
        acc[j] = lo + hi;
    }
    // tail t=40, window f[12..18]
    #pragma unroll
    for (int c = 0; c < OUT_CH; c++) {
        float s = scb[c];
        #pragma unroll
        for (int k = 0; k < KW; k++) s = fmaf(scw[c * KW + k], f[12 + k], s);
        float cv = fmaxf(s, 0.f);
        const float4* wr = (const float4*)&sWl[c * HID];
        #pragma unroll
        for (int q2 = 0; q2 < 4; q2++) {
            float4 w = wr[q2];
            acc[q2 * 4 + 0] = fmaf(w.x, cv, acc[q2 * 4 + 0]);
            acc[q2 * 4 + 1] = fmaf(w.y, cv, acc[q2 * 4 + 1]);
            acc[q2 * 4 + 2] = fmaf(w.z, cv, acc[q2 * 4 + 2]);
            acc[q2 * 4 + 3] = fmaf(w.w, cv, acc[q2 * 4 + 3]);
        }
    }

    float4* p1 = (float4*)&g_p1[(size_t)v * HID];
    #pragma unroll
    for (int q = 0; q < 4; q++)
        p1[q] = make_float4(acc[q * 4], acc[q * 4 + 1], acc[q * 4 + 2], acc[q * 4 + 3]);
}

// ============================================================
// Fused: CSR aggregate over p1 + GIN1 MLP + g2w1 projection -> p2
// Warp per node; 4 lanes per edge (float4 quarter each).
// ============================================================
__global__ __launch_bounds__(256) void k_agg_gin1(const float* __restrict__ g1b1,
                                                  const float* __restrict__ g1w2,
                                                  const float* __restrict__ g1b2,
                                                  const float* __restrict__ g2w1) {
    __shared__ float sw2[HID * HID], sw3[HID * HID], sb1[HID], sb2[HID];
    __shared__ float sz[8][HID + 1];
    __shared__ float sh2[8][HID + 1];
    int tid = threadIdx.x;
    if (tid < HID * HID) { sw2[tid] = g1w2[tid]; sw3[tid] = g2w1[tid]; }
    if (tid < HID) { sb1[tid] = g1b1[tid]; sb2[tid] = g1b2[tid]; }
    __syncthreads();

    int w = tid >> 5, lane = tid & 31;
    int v = blockIdx.x * 8 + w;
    if (v >= NN) return;
    int start = __ldg(&g_off[v]);
    int end   = __ldg(&g_off[v + 1]);
    int q  = lane & 3;
    int es = lane >> 2;
    float4 acc = make_float4(0.f, 0.f, 0.f, 0.f);
    for (int e0 = start; e0 < end; e0 += 8) {
        int e = e0 + es;
        if (e < end) {
            int s = __ldg(&g_sorted[e]);
            float4 t = __ldg(&((const float4*)(g_p1 + (size_t)s * HID))[q]);
            acc.x += t.x; acc.y += t.y; acc.z += t.z; acc.w += t.w;
        }
    }
    #pragma unroll
    for (int off = 4; off < 32; off <<= 1) {
        acc.x += __shfl_xor_sync(0xffffffffu, acc.x, off);
        acc.y += __shfl_xor_sync(0xffffffffu, acc.y, off);
        acc.z += __shfl_xor_sync(0xffffffffu, acc.z, off);
        acc.w += __shfl_xor_sync(0xffffffffu, acc.w, off);
    }
    if (lane < 4) {
        float4 pv = __ldg(&((const float4*)(g_p1 + (size_t)v * HID))[lane]);
        sz[w][lane * 4 + 0] = fmaxf(pv.x + acc.x + sb1[lane * 4 + 0], 0.f);
        sz[w][lane * 4 + 1] = fmaxf(pv.y + acc.y + sb1[lane * 4 + 1], 0.f);
        sz[w][lane * 4 + 2] = fmaxf(pv.z + acc.z + sb1[lane * 4 + 2], 0.f);
        sz[w][lane * 4 + 3] = fmaxf(pv.w + acc.w + sb1[lane * 4 + 3], 0.f);
    }
    __syncwarp();
    if (lane < HID) {
        float s = sb2[lane];
        #pragma unroll
        for (int j = 0; j < HID; j++) s = fmaf(sz[w][j], sw2[lane * HID + j], s);
        sh2[w][lane] = fmaxf(s, 0.f);
    }
    __syncwarp();
    if (lane < HID) {
        float s = 0.f;
        #pragma unroll
        for (int k = 0; k < HID; k++) s = fmaf(sh2[w][k], sw3[lane * HID + k], s);
        g_p2[(size_t)v * HID + lane] = s;
    }
}

// ============================================================
// Fused: CSR aggregate over p2 + readout -> out
// ============================================================
__global__ __launch_bounds__(256) void k_agg_out(const float* __restrict__ g2b1,
                                                 float* __restrict__ out) {
    __shared__ float sw[HID], sb[HID];
    int tid = threadIdx.x;
    if (tid < HID) { sw[tid] = g_wout[tid]; sb[tid] = g2b1[tid]; }
    __syncthreads();

    int w = tid >> 5, lane = tid & 31;
    int v = blockIdx.x * 8 + w;
    if (v >= NN) return;
    int start = __ldg(&g_off[v]);
    int end   = __ldg(&g_off[v + 1]);
    int q  = lane & 3;
    int es = lane >> 2;
    float4 acc = make_float4(0.f, 0.f, 0.f, 0.f);
    for (int e0 = start; e0 < end; e0 += 8) {
        int e = e0 + es;
        if (e < end) {
            int s = __ldg(&g_sorted[e]);
            float4 t = __ldg(&((const float4*)(g_p2 + (size_t)s * HID))[q]);
            acc.x += t.x; acc.y += t.y; acc.z += t.z; acc.w += t.w;
        }
    }
    #pragma unroll
    for (int off = 4; off < 32; off <<= 1) {
        acc.x += __shfl_xor_sync(0xffffffffu, acc.x, off);
        acc.y += __shfl_xor_sync(0xffffffffu, acc.y, off);
        acc.z += __shfl_xor_sync(0xffffffffu, acc.z, off);
        acc.w += __shfl_xor_sync(0xffffffffu, acc.w, off);
    }
    if (lane < 4) {
        float4 pv = __ldg(&((const float4*)(g_p2 + (size_t)v * HID))[lane]);
        float s;
        s  = fmaxf(pv.x + acc.x + sb[lane * 4 + 0], 0.f) * sw[lane * 4 + 0];
        s  = fmaf(fmaxf(pv.y + acc.y + sb[lane * 4 + 1], 0.f), sw[lane * 4 + 1], s);
        s  = fmaf(fmaxf(pv.z + acc.z + sb[lane * 4 + 2], 0.f), sw[lane * 4 + 2], s);
        s  = fmaf(fmaxf(pv.w + acc.w + sb[lane * 4 + 3], 0.f), sw[lane * 4 + 3], s);
        s += __shfl_xor_sync(0x0000000fu, s, 1);
        s += __shfl_xor_sync(0x0000000fu, s, 2);
        if (lane == 0) out[v] = s + g_bout;
    }
}

extern "C" void kernel_launch(void* const* d_in, const int* in_sizes, int n_in,
                              void* d_out, int out_size) {
    const float* x       = (const float*)d_in[0];
    const int*   ei      = (const int*)d_in[1];      // int32 (JAX x64 off)
    const float* conv_w  = (const float*)d_in[2];
    const float* conv_b  = (const float*)d_in[3];
    const float* fc_w    = (const float*)d_in[4];
    const float* fc_b    = (const float*)d_in[5];
    const float* g1w1    = (const float*)d_in[6];
    const float* g1b1    = (const float*)d_in[7];
    const float* g1w2    = (const float*)d_in[8];
    const float* g1b2    = (const float*)d_in[9];
    const float* g2w1    = (const float*)d_in[10];
    const float* g2b1    = (const float*)d_in[11];
    const float* g2w2    = (const float*)d_in[12];
    const float* g2b2    = (const float*)d_in[13];
    const float* ro_w    = (const float*)d_in[14];
    const float* ro_b    = (const float*)d_in[15];
    float* out = (float*)d_out;

    int n  = in_sizes[0] / T_LEN;   // 100000
    int nE = in_sizes[1] / 2;       // 3200000

    k_setup<<<1, 256>>>(fc_w, fc_b, g1w1, g2w2, g2b2, ro_w, ro_b);
    k_zero<<<(NN + 255) / 256, 256>>>();
    k_hist<<<(nE + 255) / 256, 256>>>(ei, nE);
    k_scan1<<<NBLK, SCAN_BLK>>>();
    k_scan2<<<1, 128>>>();
    k_scan3<<<NBLK, SCAN_BLK>>>();
    k_reorder<<<(nE + 255) / 256, 256>>>(ei, nE);
    k_temporal<<<(n + 127) / 128, 128>>>(x, conv_w, conv_b, n);
    k_agg_gin1<<<(NN + 7) / 8, 256>>>(g1b1, g1w2, g1b2, g2w1);
    k_agg_out<<<(NN + 7) / 8, 256>>>(g2b1, out);
}

// round 12
// speedup vs baseline: 1.0167x; 1.0167x over previous
#include <cuda_runtime.h>
#include <cstdint>

#define NN 100000
#define NE_MAX 3200000
#define T_LEN 128
#define OUT_CH 5
#define KW 7
#define L_OUT 41
#define FLAT 205
#define EMB 32
#define HID 16

#define SCAN_BLK 256
#define SCAN_ITEMS 4
#define SCAN_CHUNK (SCAN_BLK * SCAN_ITEMS)          // 1024
#define NBLK ((NN + SCAN_CHUNK - 1) / SCAN_CHUNK)   // 98

// ---- device scratch ----
__device__ __align__(16) float g_p1[NN * HID];
__device__ __align__(16) float g_p2[NN * HID];
__device__ __align__(16) float g_Wc[FLAT * HID];
__device__ float g_bfc[HID];
__device__ float g_wout[HID];
__device__ float g_bout;

// CSR sort scratch
__device__ int g_deg[NN];
__device__ int g_off[NN + 1];
__device__ int g_cur[NN];
__device__ int g_blksum[NBLK];
__device__ int g_sorted[NE_MAX];

// ============================================================
// Setup: fold fc->g1w1 and g2w2->ro into combined weights.
// ============================================================
__global__ void k_setup(const float* __restrict__ fc_w, const float* __restrict__ fc_b,
                        const float* __restrict__ g1w1,
                        const float* __restrict__ g2w2, const float* __restrict__ g2b2,
                        const float* __restrict__ ro_w, const float* __restrict__ ro_b) {
    int tid = threadIdx.x;
    for (int idx = tid; idx < FLAT * HID; idx += blockDim.x) {
        int i = idx >> 4, j = idx & 15;
        float s = 0.f;
        #pragma unroll
        for (int k = 0; k < EMB; k++) s = fmaf(g1w1[j * EMB + k], fc_w[k * FLAT + i], s);
        g_Wc[idx] = s;
    }
    if (tid < HID) {
        float s = 0.f;
        #pragma unroll
        for (int k = 0; k < EMB; k++) s = fmaf(g1w1[tid * EMB + k], fc_b[k], s);
        g_bfc[tid] = s;
        float w = 0.f;
        #pragma unroll
        for (int k = 0; k < HID; k++) w = fmaf(ro_w[k], g2w2[k * HID + tid], w);
        g_wout[tid] = w;
    }
    if (tid == 0) {
        float b = ro_b[0];
        #pragma unroll
        for (int k = 0; k < HID; k++) b = fmaf(ro_w[k], g2b2[k], b);
        g_bout = b;
    }
}

// ============================================================
// CSR build
// ============================================================
__global__ void k_zero() {
    int i = blockIdx.x * 256 + threadIdx.x;
    if (i < NN) g_deg[i] = 0;
}

__global__ void k_hist(const int* __restrict__ ei, int nE) {
    int e = blockIdx.x * 256 + threadIdx.x;
    if (e < nE) atomicAdd(&g_deg[__ldg(&ei[(size_t)nE + e])], 1);
}

// block sums via shfl reduction
__global__ void k_scan1() {
    __shared__ int swp[8];
    int t = threadIdx.x, b = blockIdx.x;
    int lane = t & 31, w = t >> 5;
    int base = b * SCAN_CHUNK + t * SCAN_ITEMS;
    int s = 0;
    #pragma unroll
    for (int i = 0; i < SCAN_ITEMS; i++) {
        int idx = base + i;
        if (idx < NN) s += g_deg[idx];
    }
    #pragma unroll
    for (int off = 16; off > 0; off >>= 1) s += __shfl_xor_sync(0xffffffffu, s, off);
    if (lane == 0) swp[w] = s;
    __syncthreads();
    if (t < 8) {
        int v = swp[t];
        #pragma unroll
        for (int off = 4; off > 0; off >>= 1) v += __shfl_xor_sync(0xffu, v, off);
        if (t == 0) g_blksum[b] = v;
    }
}

// exclusive scan of 98 block sums (1 block, 128 thr)
__global__ void k_scan2() {
    __shared__ int swp[4];
    int t = threadIdx.x, lane = t & 31, w = t >> 5;
    int v = (t < NBLK) ? g_blksum[t] : 0;
    int incl = v;
    #pragma unroll
    for (int off = 1; off < 32; off <<= 1) {
        int u = __shfl_up_sync(0xffffffffu, incl, off);
        if (lane >= off) incl += u;
    }
    if (lane == 31) swp[w] = incl;
    __syncthreads();
    int basew = 0;
    for (int i = 0; i < w; i++) basew += swp[i];
    incl += basew;
    if (t < NBLK) g_blksum[t] = incl - v;
    if (t == 127) g_off[NN] = incl;
}

__global__ void k_scan3() {
    __shared__ int swp[8];
    int t = threadIdx.x, b = blockIdx.x;
    int lane = t & 31, w = t >> 5;
    int base = b * SCAN_CHUNK + t * SCAN_ITEMS;
    int d[SCAN_ITEMS]; int s = 0;
    #pragma unroll
    for (int i = 0; i < SCAN_ITEMS; i++) {
        int idx = base + i;
        d[i] = (idx < NN) ? g_deg[idx] : 0;
        s += d[i];
    }
    int incl = s;
    #pragma unroll
    for (int off = 1; off < 32; off <<= 1) {
        int u = __shfl_up_sync(0xffffffffu, incl, off);
        if (lane >= off) incl += u;
    }
    if (lane == 31) swp[w] = incl;
    __syncthreads();
    int basew = g_blksum[b];
    for (int i = 0; i < w; i++) basew += swp[i];
    int excl = basew + incl - s;
    #pragma unroll
    for (int i = 0; i < SCAN_ITEMS; i++) {
        int idx = base + i;
        if (idx < NN) {
            g_off[idx] = excl;
            g_cur[idx] = excl;
            excl += d[i];
        }
    }
}

__global__ void k_reorder(const int* __restrict__ ei, int nE) {
    int e = blockIdx.x * 256 + threadIdx.x;
    if (e >= nE) return;
    int dst = __ldg(&ei[(size_t)nE + e]);
    int pos = atomicAdd(&g_cur[dst], 1);
    g_sorted[pos] = __ldg(&ei[e]);
}

// ============================================================
// Temporal: conv1d(+ReLU) fused with combined 205->16 matmul.
// (R6 scalar version — known good)
// ============================================================
__global__ __launch_bounds__(128) void k_temporal(const float* __restrict__ x,
                                                  const float* __restrict__ conv_w,
                                                  const float* __restrict__ conv_b,
                                                  int n) {
    __shared__ __align__(16) float sW[FLAT * HID];
    __shared__ float scw[OUT_CH * KW];
    __shared__ float scb[OUT_CH];
    __shared__ float sbf[HID];
    int tid = threadIdx.x;
    for (int i = tid; i < FLAT * HID; i += 128) sW[i] = g_Wc[i];
    if (tid < OUT_CH * KW) scw[tid] = conv_w[tid];
    if (tid < OUT_CH) scb[tid] = conv_b[tid];
    if (tid < HID) sbf[tid] = g_bfc[tid];
    __syncthreads();

    int v = blockIdx.x * 128 + tid;
    if (v >= n) return;

    const float4* x4 = (const float4*)(x + (size_t)v * T_LEN);
    float acc[HID];
    #pragma unroll
    for (int j = 0; j < HID; j++) acc[j] = sbf[j];

    float f[20];
    #pragma unroll
    for (int q = 0; q < 5; q++) {
        float4 t4 = __ldg(&x4[q]);
        f[q * 4] = t4.x; f[q * 4 + 1] = t4.y; f[q * 4 + 2] = t4.z; f[q * 4 + 3] = t4.w;
    }

    for (int g = 0; g < 10; g++) {
        #pragma unroll
        for (int tl = 0; tl < 4; tl++) {
            int t = g * 4 + tl;
            float cv[OUT_CH];
            #pragma unroll
            for (int c = 0; c < OUT_CH; c++) {
                float s = scb[c];
                #pragma unroll
                for (int k = 0; k < KW; k++) s = fmaf(scw[c * KW + k], f[3 * tl + k], s);
                cv[c] = fmaxf(s, 0.f);
            }
            #pragma unroll
            for (int c = 0; c < OUT_CH; c++) {
                const float4* wr = (const float4*)&sW[(c * L_OUT + t) * HID];
                #pragma unroll
                for (int q2 = 0; q2 < 4; q2++) {
                    float4 w = wr[q2];
                    acc[q2 * 4 + 0] = fmaf(w.x, cv[c], acc[q2 * 4 + 0]);
                    acc[q2 * 4 + 1] = fmaf(w.y, cv[c], acc[q2 * 4 + 1]);
                    acc[q2 * 4 + 2] = fmaf(w.z, cv[c], acc[q2 * 4 + 2]);
                    acc[q2 * 4 + 3] = fmaf(w.w, cv[c], acc[q2 * 4 + 3]);
                }
            }
        }
        if (g != 9) {
            #pragma unroll
            for (int i = 0; i < 8; i++) f[i] = f[i + 12];
            #pragma unroll
            for (int q = 0; q < 3; q++) {
                float4 t4 = __ldg(&x4[3 * g + 5 + q]);
                f[8 + q * 4] = t4.x; f[9 + q * 4] = t4.y; f[10 + q * 4] = t4.z; f[11 + q * 4] = t4.w;
            }
        }
    }
    {
        float cv[OUT_CH];
        #pragma unroll
        for (int c = 0; c < OUT_CH; c++) {
            float s = scb[c];
            #pragma unroll
            for (int k = 0; k < KW; k++) s = fmaf(scw[c * KW + k], f[12 + k], s);
            cv[c] = fmaxf(s, 0.f);
        }
        #pragma unroll
        for (int c = 0; c < OUT_CH; c++) {
            const float4* wr = (const float4*)&sW[(c * L_OUT + 40) * HID];
            #pragma unroll
            for (int q2 = 0; q2 < 4; q2++) {
                float4 w = wr[q2];
                acc[q2 * 4 + 0] = fmaf(w.x, cv[c], acc[q2 * 4 + 0]);
                acc[q2 * 4 + 1] = fmaf(w.y, cv[c], acc[q2 * 4 + 1]);
                acc[q2 * 4 + 2] = fmaf(w.z, cv[c], acc[q2 * 4 + 2]);
                acc[q2 * 4 + 3] = fmaf(w.w, cv[c], acc[q2 * 4 + 3]);
            }
        }
    }

    float4* p1 = (float4*)&g_p1[(size_t)v * HID];
    #pragma unroll
    for (int q = 0; q < 4; q++)
        p1[q] = make_float4(acc[q * 4], acc[q * 4 + 1], acc[q * 4 + 2], acc[q * 4 + 3]);
}

// ============================================================
// Fused: CSR aggregate over p1 + GIN1 MLP + g2w1 projection -> p2
// ============================================================
__global__ __launch_bounds__(256) void k_agg_gin1(const float* __restrict__ g1b1,
                                                  const float* __restrict__ g1w2,
                                                  const float* __restrict__ g1b2,
                                                  const float* __restrict__ g2w1) {
    __shared__ float sw2[HID * HID], sw3[HID * HID], sb1[HID], sb2[HID];
    __shared__ float sz[8][HID + 1];
    __shared__ float sh2[8][HID + 1];
    int tid = threadIdx.x;
    if (tid < HID * HID) { sw2[tid] = g1w2[tid]; sw3[tid] = g2w1[tid]; }
    if (tid < HID) { sb1[tid] = g1b1[tid]; sb2[tid] = g1b2[tid]; }
    __syncthreads();

    int w = tid >> 5, lane = tid & 31;
    int v = blockIdx.x * 8 + w;
    if (v >= NN) return;
    int start = __ldg(&g_off[v]);
    int end   = __ldg(&g_off[v + 1]);
    int q  = lane & 3;
    int es = lane >> 2;
    float4 acc = make_float4(0.f, 0.f, 0.f, 0.f);
    for (int e0 = start; e0 < end; e0 += 8) {
        int e = e0 + es;
        if (e < end) {
            int s = __ldg(&g_sorted[e]);
            float4 t = __ldg(&((const float4*)(g_p1 + (size_t)s * HID))[q]);
            acc.x += t.x; acc.y += t.y; acc.z += t.z; acc.w += t.w;
        }
    }
    #pragma unroll
    for (int off = 4; off < 32; off <<= 1) {
        acc.x += __shfl_xor_sync(0xffffffffu, acc.x, off);
        acc.y += __shfl_xor_sync(0xffffffffu, acc.y, off);
        acc.z += __shfl_xor_sync(0xffffffffu, acc.z, off);
        acc.w += __shfl_xor_sync(0xffffffffu, acc.w, off);
    }
    if (lane < 4) {
        float4 pv = __ldg(&((const float4*)(g_p1 + (size_t)v * HID))[lane]);
        sz[w][lane * 4 + 0] = fmaxf(pv.x + acc.x + sb1[lane * 4 + 0], 0.f);
        sz[w][lane * 4 + 1] = fmaxf(pv.y + acc.y + sb1[lane * 4 + 1], 0.f);
        sz[w][lane * 4 + 2] = fmaxf(pv.z + acc.z + sb1[lane * 4 + 2], 0.f);
        sz[w][lane * 4 + 3] = fmaxf(pv.w + acc.w + sb1[lane * 4 + 3], 0.f);
    }
    __syncwarp();
    if (lane < HID) {
        float s = sb2[lane];
        #pragma unroll
        for (int j = 0; j < HID; j++) s = fmaf(sz[w][j], sw2[lane * HID + j], s);
        sh2[w][lane] = fmaxf(s, 0.f);
    }
    __syncwarp();
    if (lane < HID) {
        float s = 0.f;
        #pragma unroll
        for (int k = 0; k < HID; k++) s = fmaf(sh2[w][k], sw3[lane * HID + k], s);
        g_p2[(size_t)v * HID + lane] = s;
    }
}

// ============================================================
// Fused: CSR aggregate over p2 + readout -> out
// ============================================================
__global__ __launch_bounds__(256) void k_agg_out(const float* __restrict__ g2b1,
                                                 float* __restrict__ out) {
    __shared__ float sw[HID], sb[HID];
    int tid = threadIdx.x;
    if (tid < HID) { sw[tid] = g_wout[tid]; sb[tid] = g2b1[tid]; }
    __syncthreads();

    int w = tid >> 5, lane = tid & 31;
    int v = blockIdx.x * 8 + w;
    if (v >= NN) return;
    int start = __ldg(&g_off[v]);
    int end   = __ldg(&g_off[v + 1]);
    int q  = lane & 3;
    int es = lane >> 2;
    float4 acc = make_float4(0.f, 0.f, 0.f, 0.f);
    for (int e0 = start; e0 < end; e0 += 8) {
        int e = e0 + es;
        if (e < end) {
            int s = __ldg(&g_sorted[e]);
            float4 t = __ldg(&((const float4*)(g_p2 + (size_t)s * HID))[q]);
            acc.x += t.x; acc.y += t.y; acc.z += t.z; acc.w += t.w;
        }
    }
    #pragma unroll
    for (int off = 4; off < 32; off <<= 1) {
        acc.x += __shfl_xor_sync(0xffffffffu, acc.x, off);
        acc.y += __shfl_xor_sync(0xffffffffu, acc.y, off);
        acc.z += __shfl_xor_sync(0xffffffffu, acc.z, off);
        acc.w += __shfl_xor_sync(0xffffffffu, acc.w, off);
    }
    if (lane < 4) {
        float4 pv = __ldg(&((const float4*)(g_p2 + (size_t)v * HID))[lane]);
        float s;
        s  = fmaxf(pv.x + acc.x + sb[lane * 4 + 0], 0.f) * sw[lane * 4 + 0];
        s  = fmaf(fmaxf(pv.y + acc.y + sb[lane * 4 + 1], 0.f), sw[lane * 4 + 1], s);
        s  = fmaf(fmaxf(pv.z + acc.z + sb[lane * 4 + 2], 0.f), sw[lane * 4 + 2], s);
        s  = fmaf(fmaxf(pv.w + acc.w + sb[lane * 4 + 3], 0.f), sw[lane * 4 + 3], s);
        s += __shfl_xor_sync(0x0000000fu, s, 1);
        s += __shfl_xor_sync(0x0000000fu, s, 2);
        if (lane == 0) out[v] = s + g_bout;
    }
}

extern "C" void kernel_launch(void* const* d_in, const int* in_sizes, int n_in,
                              void* d_out, int out_size) {
    const float* x       = (const float*)d_in[0];
    const int*   ei      = (const int*)d_in[1];      // int32 (JAX x64 off)
    const float* conv_w  = (const float*)d_in[2];
    const float* conv_b  = (const float*)d_in[3];
    const float* fc_w    = (const float*)d_in[4];
    const float* fc_b    = (const float*)d_in[5];
    const float* g1w1    = (const float*)d_in[6];
    const float* g1b1    = (const float*)d_in[7];
    const float* g1w2    = (const float*)d_in[8];
    const float* g1b2    = (const float*)d_in[9];
    const float* g2w1    = (const float*)d_in[10];
    const float* g2b1    = (const float*)d_in[11];
    const float* g2w2    = (const float*)d_in[12];
    const float* g2b2    = (const float*)d_in[13];
    const float* ro_w    = (const float*)d_in[14];
    const float* ro_b    = (const float*)d_in[15];
    float* out = (float*)d_out;

    int n  = in_sizes[0] / T_LEN;   // 100000
    int nE = in_sizes[1] / 2;       // 3200000

    k_setup<<<1, 256>>>(fc_w, fc_b, g1w1, g2w2, g2b2, ro_w, ro_b);
    k_zero<<<(NN + 255) / 256, 256>>>();
    k_hist<<<(nE + 255) / 256, 256>>>(ei, nE);
    k_scan1<<<NBLK, SCAN_BLK>>>();
    k_scan2<<<1, 128>>>();
    k_scan3<<<NBLK, SCAN_BLK>>>();
    k_reorder<<<(nE + 255) / 256, 256>>>(ei, nE);
    k_temporal<<<(n + 127) / 128, 128>>>(x, conv_w, conv_b, n);
    k_agg_gin1<<<(NN + 7) / 8, 256>>>(g1b1, g1w2, g1b2, g2w1);
    k_agg_out<<<(NN + 7) / 8, 256>>>(g2b1, out);
}

// round 14
// speedup vs baseline: 1.1283x; 1.1098x over previous
#include <cuda_runtime.h>
#include <cstdint>

#define NN 100000
#define NE_MAX 3200000
#define T_LEN 128
#define OUT_CH 5
#define KW 7
#define L_OUT 41
#define FLAT 205
#define EMB 32
#define HID 16

#define SCAN_BLK 256
#define SCAN_ITEMS 4
#define SCAN_CHUNK (SCAN_BLK * SCAN_ITEMS)          // 1024
#define NBLK ((NN + SCAN_CHUNK - 1) / SCAN_CHUNK)   // 98

// ---- device scratch ----
__device__ __align__(16) float g_p1[NN * HID];
__device__ __align__(16) float g_agg1[NN * HID];
__device__ __align__(16) float g_p2[NN * HID];
__device__ __align__(16) float g_agg2[NN * HID];
__device__ __align__(16) float g_Wc[FLAT * HID];
__device__ float g_bfc[HID];
__device__ float g_wout[HID];
__device__ float g_bout;

// CSR sort scratch
__device__ int g_deg[NN];
__device__ int g_off[NN + 1];
__device__ int g_cur[NN];
__device__ int g_blksum[NBLK];
__device__ int g_sorted[NE_MAX];

// ============================================================
// Setup: fold fc->g1w1 and g2w2->ro into combined weights.
// ============================================================
__global__ void k_setup(const float* __restrict__ fc_w, const float* __restrict__ fc_b,
                        const float* __restrict__ g1w1,
                        const float* __restrict__ g2w2, const float* __restrict__ g2b2,
                        const float* __restrict__ ro_w, const float* __restrict__ ro_b) {
    int tid = threadIdx.x;
    for (int idx = tid; idx < FLAT * HID; idx += blockDim.x) {
        int i = idx >> 4, j = idx & 15;
        float s = 0.f;
        #pragma unroll
        for (int k = 0; k < EMB; k++) s = fmaf(g1w1[j * EMB + k], fc_w[k * FLAT + i], s);
        g_Wc[idx] = s;
    }
    if (tid < HID) {
        float s = 0.f;
        #pragma unroll
        for (int k = 0; k < EMB; k++) s = fmaf(g1w1[tid * EMB + k], fc_b[k], s);
        g_bfc[tid] = s;
        float w = 0.f;
        #pragma unroll
        for (int k = 0; k < HID; k++) w = fmaf(ro_w[k], g2w2[k * HID + tid], w);
        g_wout[tid] = w;
    }
    if (tid == 0) {
        float b = ro_b[0];
        #pragma unroll
        for (int k = 0; k < HID; k++) b = fmaf(ro_w[k], g2b2[k], b);
        g_bout = b;
    }
}

// ============================================================
// CSR build
// ============================================================
__global__ void k_zero() {
    int i = blockIdx.x * 256 + threadIdx.x;
    if (i < NN) g_deg[i] = 0;
}

__global__ void k_hist(const int* __restrict__ ei, int nE) {
    int e = blockIdx.x * 256 + threadIdx.x;
    if (e < nE) atomicAdd(&g_deg[__ldg(&ei[(size_t)nE + e])], 1);
}

// block sums via shfl reduction
__global__ void k_scan1() {
    __shared__ int swp[8];
    int t = threadIdx.x, b = blockIdx.x;
    int lane = t & 31, w = t >> 5;
    int base = b * SCAN_CHUNK + t * SCAN_ITEMS;
    int s = 0;
    #pragma unroll
    for (int i = 0; i < SCAN_ITEMS; i++) {
        int idx = base + i;
        if (idx < NN) s += g_deg[idx];
    }
    #pragma unroll
    for (int off = 16; off > 0; off >>= 1) s += __shfl_xor_sync(0xffffffffu, s, off);
    if (lane == 0) swp[w] = s;
    __syncthreads();
    if (t < 8) {
        int v = swp[t];
        #pragma unroll
        for (int off = 4; off > 0; off >>= 1) v += __shfl_xor_sync(0xffu, v, off);
        if (t == 0) g_blksum[b] = v;
    }
}

// exclusive scan of 98 block sums (1 block, 128 thr)
__global__ void k_scan2() {
    __shared__ int swp[4];
    int t = threadIdx.x, lane = t & 31, w = t >> 5;
    int v = (t < NBLK) ? g_blksum[t] : 0;
    int incl = v;
    #pragma unroll
    for (int off = 1; off < 32; off <<= 1) {
        int u = __shfl_up_sync(0xffffffffu, incl, off);
        if (lane >= off) incl += u;
    }
    if (lane == 31) swp[w] = incl;
    __syncthreads();
    int basew = 0;
    for (int i = 0; i < w; i++) basew += swp[i];
    incl += basew;
    if (t < NBLK) g_blksum[t] = incl - v;
    if (t == 127) g_off[NN] = incl;
}

__global__ void k_scan3() {
    __shared__ int swp[8];
    int t = threadIdx.x, b = blockIdx.x;
    int lane = t & 31, w = t >> 5;
    int base = b * SCAN_CHUNK + t * SCAN_ITEMS;
    int d[SCAN_ITEMS]; int s = 0;
    #pragma unroll
    for (int i = 0; i < SCAN_ITEMS; i++) {
        int idx = base + i;
        d[i] = (idx < NN) ? g_deg[idx] : 0;
        s += d[i];
    }
    int incl = s;
    #pragma unroll
    for (int off = 1; off < 32; off <<= 1) {
        int u = __shfl_up_sync(0xffffffffu, incl, off);
        if (lane >= off) incl += u;
    }
    if (lane == 31) swp[w] = incl;
    __syncthreads();
    int basew = g_blksum[b];
    for (int i = 0; i < w; i++) basew += swp[i];
    int excl = basew + incl - s;
    #pragma unroll
    for (int i = 0; i < SCAN_ITEMS; i++) {
        int idx = base + i;
        if (idx < NN) {
            g_off[idx] = excl;
            g_cur[idx] = excl;
            excl += d[i];
        }
    }
}

__global__ void k_reorder(const int* __restrict__ ei, int nE) {
    int e = blockIdx.x * 256 + threadIdx.x;
    if (e >= nE) return;
    int dst = __ldg(&ei[(size_t)nE + e]);
    int pos = atomicAdd(&g_cur[dst], 1);
    g_sorted[pos] = __ldg(&ei[e]);
}

// ============================================================
// Temporal: conv1d(+ReLU) fused with combined 205->16 matmul.
// (R6/R9 scalar version — known good)
// ============================================================
__global__ __launch_bounds__(128) void k_temporal(const float* __restrict__ x,
                                                  const float* __restrict__ conv_w,
                                                  const float* __restrict__ conv_b,
                                                  int n) {
    __shared__ __align__(16) float sW[FLAT * HID];
    __shared__ float scw[OUT_CH * KW];
    __shared__ float scb[OUT_CH];
    __shared__ float sbf[HID];
    int tid = threadIdx.x;
    for (int i = tid; i < FLAT * HID; i += 128) sW[i] = g_Wc[i];
    if (tid < OUT_CH * KW) scw[tid] = conv_w[tid];
    if (tid < OUT_CH) scb[tid] = conv_b[tid];
    if (tid < HID) sbf[tid] = g_bfc[tid];
    __syncthreads();

    int v = blockIdx.x * 128 + tid;
    if (v >= n) return;

    const float4* x4 = (const float4*)(x + (size_t)v * T_LEN);
    float acc[HID];
    #pragma unroll
    for (int j = 0; j < HID; j++) acc[j] = sbf[j];

    float f[20];
    #pragma unroll
    for (int q = 0; q < 5; q++) {
        float4 t4 = __ldg(&x4[q]);
        f[q * 4] = t4.x; f[q * 4 + 1] = t4.y; f[q * 4 + 2] = t4.z; f[q * 4 + 3] = t4.w;
    }

    for (int g = 0; g < 10; g++) {
        #pragma unroll
        for (int tl = 0; tl < 4; tl++) {
            int t = g * 4 + tl;
            float cv[OUT_CH];
            #pragma unroll
            for (int c = 0; c < OUT_CH; c++) {
                float s = scb[c];
                #pragma unroll
                for (int k = 0; k < KW; k++) s = fmaf(scw[c * KW + k], f[3 * tl + k], s);
                cv[c] = fmaxf(s, 0.f);
            }
            #pragma unroll
            for (int c = 0; c < OUT_CH; c++) {
                const float4* wr = (const float4*)&sW[(c * L_OUT + t) * HID];
                #pragma unroll
                for (int q2 = 0; q2 < 4; q2++) {
                    float4 w = wr[q2];
                    acc[q2 * 4 + 0] = fmaf(w.x, cv[c], acc[q2 * 4 + 0]);
                    acc[q2 * 4 + 1] = fmaf(w.y, cv[c], acc[q2 * 4 + 1]);
                    acc[q2 * 4 + 2] = fmaf(w.z, cv[c], acc[q2 * 4 + 2]);
                    acc[q2 * 4 + 3] = fmaf(w.w, cv[c], acc[q2 * 4 + 3]);
                }
            }
        }
        if (g != 9) {
            #pragma unroll
            for (int i = 0; i < 8; i++) f[i] = f[i + 12];
            #pragma unroll
            for (int q = 0; q < 3; q++) {
                float4 t4 = __ldg(&x4[3 * g + 5 + q]);
                f[8 + q * 4] = t4.x; f[9 + q * 4] = t4.y; f[10 + q * 4] = t4.z; f[11 + q * 4] = t4.w;
            }
        }
    }
    {
        float cv[OUT_CH];
        #pragma unroll
        for (int c = 0; c < OUT_CH; c++) {
            float s = scb[c];
            #pragma unroll
            for (int k = 0; k < KW; k++) s = fmaf(scw[c * KW + k], f[12 + k], s);
            cv[c] = fmaxf(s, 0.f);
        }
        #pragma unroll
        for (int c = 0; c < OUT_CH; c++) {
            const float4* wr = (const float4*)&sW[(c * L_OUT + 40) * HID];
            #pragma unroll
            for (int q2 = 0; q2 < 4; q2++) {
                float4 w = wr[q2];
                acc[q2 * 4 + 0] = fmaf(w.x, cv[c], acc[q2 * 4 + 0]);
                acc[q2 * 4 + 1] = fmaf(w.y, cv[c], acc[q2 * 4 + 1]);
                acc[q2 * 4 + 2] = fmaf(w.z, cv[c], acc[q2 * 4 + 2]);
                acc[q2 * 4 + 3] = fmaf(w.w, cv[c], acc[q2 * 4 + 3]);
            }
        }
    }

    float4* p1 = (float4*)&g_p1[(size_t)v * HID];
    #pragma unroll
    for (int q = 0; q < 4; q++)
        p1[q] = make_float4(acc[q * 4], acc[q * 4 + 1], acc[q * 4 + 2], acc[q * 4 + 3]);
}

// ============================================================
// CSR aggregation: warp per node, 4 lanes per edge (one float4
// quarter each), register accumulate + 12-shfl reduction.
// ============================================================
__global__ __launch_bounds__(256) void k_agg_csr(int layer) {
    const float* __restrict__ p = layer ? g_p2 : g_p1;
    float* __restrict__ agg = layer ? g_agg2 : g_agg1;
    int lane = threadIdx.x & 31;
    int v = blockIdx.x * 8 + (threadIdx.x >> 5);
    if (v >= NN) return;
    int start = __ldg(&g_off[v]);
    int end   = __ldg(&g_off[v + 1]);
    int q  = lane & 3;
    int es = lane >> 2;
    float4 acc = make_float4(0.f, 0.f, 0.f, 0.f);
    for (int e0 = start; e0 < end; e0 += 8) {
        int e = e0 + es;
        if (e < end) {
            int s = __ldg(&g_sorted[e]);
            float4 t = __ldg(&((const float4*)(p + (size_t)s * HID))[q]);
            acc.x += t.x; acc.y += t.y; acc.z += t.z; acc.w += t.w;
        }
    }
    #pragma unroll
    for (int off = 4; off < 32; off <<= 1) {
        acc.x += __shfl_xor_sync(0xffffffffu, acc.x, off);
        acc.y += __shfl_xor_sync(0xffffffffu, acc.y, off);
        acc.z += __shfl_xor_sync(0xffffffffu, acc.z, off);
        acc.w += __shfl_xor_sync(0xffffffffu, acc.w, off);
    }
    if (lane < 4) ((float4*)(agg + (size_t)v * HID))[lane] = acc;
}

// ============================================================
// GIN1 node update
// ============================================================
__global__ __launch_bounds__(256) void k_gin1(const float* __restrict__ g1b1,
                                              const float* __restrict__ g1w2,
                                              const float* __restrict__ g1b2,
                                              const float* __restrict__ g2w1, int n) {
    __shared__ float sw2[HID * HID], sw3[HID * HID], sb1[HID], sb2[HID];
    int tid = threadIdx.x;
    if (tid < HID * HID) { sw2[tid] = g1w2[tid]; sw3[tid] = g2w1[tid]; }
    if (tid < HID) { sb1[tid] = g1b1[tid]; sb2[tid] = g1b2[tid]; }
    __syncthreads();
    int v = blockIdx.x * 256 + tid;
    if (v >= n) return;

    const float4* p1 = (const float4*)&g_p1[(size_t)v * HID];
    const float4* a1 = (const float4*)&g_agg1[(size_t)v * HID];
    float q[HID];
    #pragma unroll
    for (int i = 0; i < 4; i++) {
        float4 pv = p1[i], av = a1[i];
        q[i * 4 + 0] = fmaxf(pv.x + av.x + sb1[i * 4 + 0], 0.f);
        q[i * 4 + 1] = fmaxf(pv.y + av.y + sb1[i * 4 + 1], 0.f);
        q[i * 4 + 2] = fmaxf(pv.z + av.z + sb1[i * 4 + 2], 0.f);
        q[i * 4 + 3] = fmaxf(pv.w + av.w + sb1[i * 4 + 3], 0.f);
    }
    float h2[HID];
    #pragma unroll
    for (int k = 0; k < HID; k++) {
        float s = sb2[k];
        #pragma unroll
        for (int j = 0; j < HID; j++) s = fmaf(q[j], sw2[k * HID + j], s);
        h2[k] = fmaxf(s, 0.f);
    }
    float4* p2 = (float4*)&g_p2[(size_t)v * HID];
    #pragma unroll
    for (int i = 0; i < 4; i++) {
        float o[4];
        #pragma unroll
        for (int u = 0; u < 4; u++) {
            int j = i * 4 + u;
            float s = 0.f;
            #pragma unroll
            for (int k = 0; k < HID; k++) s = fmaf(h2[k], sw3[j * HID + k], s);
            o[u] = s;
        }
        p2[i] = make_float4(o[0], o[1], o[2], o[3]);
    }
}

// ============================================================
// Output
// ============================================================
__global__ __launch_bounds__(256) void k_out(const float* __restrict__ g2b1,
                                             float* __restrict__ out, int n) {
    __shared__ float sw[HID], sb[HID];
    int tid = threadIdx.x;
    if (tid < HID) { sw[tid] = g_wout[tid]; sb[tid] = g2b1[tid]; }
    __syncthreads();
    int v = blockIdx.x * 256 + tid;
    if (v >= n) return;
    const float4* p2 = (const float4*)&g_p2[(size_t)v * HID];
    const float4* a2 = (const float4*)&g_agg2[(size_t)v * HID];
    float s = g_bout;
    #pragma unroll
    for (int i = 0; i < 4; i++) {
        float4 pv = p2[i], av = a2[i];
        s = fmaf(fmaxf(pv.x + av.x + sb[i * 4 + 0], 0.f), sw[i * 4 + 0], s);
        s = fmaf(fmaxf(pv.y + av.y + sb[i * 4 + 1], 0.f), sw[i * 4 + 1], s);
        s = fmaf(fmaxf(pv.z + av.z + sb[i * 4 + 2], 0.f), sw[i * 4 + 2], s);
        s = fmaf(fmaxf(pv.w + av.w + sb[i * 4 + 3], 0.f), sw[i * 4 + 3], s);
    }
    out[v] = s;
}

extern "C" void kernel_launch(void* const* d_in, const int* in_sizes, int n_in,
                              void* d_out, int out_size) {
    const float* x       = (const float*)d_in[0];
    const int*   ei      = (const int*)d_in[1];      // int32 (JAX x64 off)
    const float* conv_w  = (const float*)d_in[2];
    const float* conv_b  = (const float*)d_in[3];
    const float* fc_w    = (const float*)d_in[4];
    const float* fc_b    = (const float*)d_in[5];
    const float* g1w1    = (const float*)d_in[6];
    const float* g1b1    = (const float*)d_in[7];
    const float* g1w2    = (const float*)d_in[8];
    const float* g1b2    = (const float*)d_in[9];
    const float* g2w1    = (const float*)d_in[10];
    const float* g2b1    = (const float*)d_in[11];
    const float* g2w2    = (const float*)d_in[12];
    const float* g2b2    = (const float*)d_in[13];
    const float* ro_w    = (const float*)d_in[14];
    const float* ro_b    = (const float*)d_in[15];
    float* out = (float*)d_out;

    int n  = in_sizes[0] / T_LEN;   // 100000
    int nE = in_sizes[1] / 2;       // 3200000

    // NOTE: k_temporal moved to launch index 3 so ncu (-s 5 -c 1, with the
    // two harness-side launches ahead of us) profiles it instead of k_scan1.
    // Dependency-safe: temporal needs only k_setup.
    k_setup<<<1, 256>>>(fc_w, fc_b, g1w1, g2w2, g2b2, ro_w, ro_b);
    k_zero<<<(NN + 255) / 256, 256>>>();
    k_hist<<<(nE + 255) / 256, 256>>>(ei, nE);
    k_temporal<<<(n + 127) / 128, 128>>>(x, conv_w, conv_b, n);
    k_scan1<<<NBLK, SCAN_BLK>>>();
    k_scan2<<<1, 128>>>();
    k_scan3<<<NBLK, SCAN_BLK>>>();
    k_reorder<<<(nE + 255) / 256, 256>>>(ei, nE);
    k_agg_csr<<<(NN + 7) / 8, 256>>>(0);
    k_gin1<<<(n + 255) / 256, 256>>>(g1b1, g1w2, g1b2, g2w1, n);
    k_agg_csr<<<(NN + 7) / 8, 256>>>(1);
    k_out<<<(n + 255) / 256, 256>>>(g2b1, out, n);
}

// round 15
// speedup vs baseline: 1.1809x; 1.0466x over previous
#include <cuda_runtime.h>
#include <cstdint>

#define NN 100000
#define NE_MAX 3200000
#define T_LEN 128
#define OUT_CH 5
#define KW 7
#define L_OUT 41
#define FLAT 205
#define EMB 32
#define HID 16

#define SCAN_BLK 256
#define SCAN_ITEMS 4
#define SCAN_CHUNK (SCAN_BLK * SCAN_ITEMS)          // 1024
#define NBLK ((NN + SCAN_CHUNK - 1) / SCAN_CHUNK)   // 98

// ---- device scratch ----
__device__ __align__(16) float g_p1[NN * HID];
__device__ __align__(16) float g_agg1[NN * HID];
__device__ __align__(16) float g_p2[NN * HID];
__device__ __align__(16) float g_agg2[NN * HID];
__device__ __align__(16) float g_Wc[FLAT * HID];
__device__ float g_bfc[HID];
__device__ float g_wout[HID];
__device__ float g_bout;

// CSR sort scratch
__device__ int g_deg[NN];
__device__ int g_off[NN + 1];
__device__ int g_cur[NN];
__device__ int g_blksum[NBLK];
__device__ int g_sorted[NE_MAX];

// ============================================================
// Setup: fold fc->g1w1 and g2w2->ro into combined weights.
// ============================================================
__global__ void k_setup(const float* __restrict__ fc_w, const float* __restrict__ fc_b,
                        const float* __restrict__ g1w1,
                        const float* __restrict__ g2w2, const float* __restrict__ g2b2,
                        const float* __restrict__ ro_w, const float* __restrict__ ro_b) {
    int tid = threadIdx.x;
    for (int idx = tid; idx < FLAT * HID; idx += blockDim.x) {
        int i = idx >> 4, j = idx & 15;
        float s = 0.f;
        #pragma unroll
        for (int k = 0; k < EMB; k++) s = fmaf(g1w1[j * EMB + k], fc_w[k * FLAT + i], s);
        g_Wc[idx] = s;
    }
    if (tid < HID) {
        float s = 0.f;
        #pragma unroll
        for (int k = 0; k < EMB; k++) s = fmaf(g1w1[tid * EMB + k], fc_b[k], s);
        g_bfc[tid] = s;
        float w = 0.f;
        #pragma unroll
        for (int k = 0; k < HID; k++) w = fmaf(ro_w[k], g2w2[k * HID + tid], w);
        g_wout[tid] = w;
    }
    if (tid == 0) {
        float b = ro_b[0];
        #pragma unroll
        for (int k = 0; k < HID; k++) b = fmaf(ro_w[k], g2b2[k], b);
        g_bout = b;
    }
}

// ============================================================
// CSR build
// ============================================================
__global__ void k_zero() {
    int i = blockIdx.x * 256 + threadIdx.x;
    if (i < NN) g_deg[i] = 0;
}

__global__ void k_hist(const int* __restrict__ ei, int nE) {
    int e = blockIdx.x * 256 + threadIdx.x;
    if (e < nE) atomicAdd(&g_deg[__ldg(&ei[(size_t)nE + e])], 1);
}

// block sums via shfl reduction
__global__ void k_scan1() {
    __shared__ int swp[8];
    int t = threadIdx.x, b = blockIdx.x;
    int lane = t & 31, w = t >> 5;
    int base = b * SCAN_CHUNK + t * SCAN_ITEMS;
    int s = 0;
    #pragma unroll
    for (int i = 0; i < SCAN_ITEMS; i++) {
        int idx = base + i;
        if (idx < NN) s += g_deg[idx];
    }
    #pragma unroll
    for (int off = 16; off > 0; off >>= 1) s += __shfl_xor_sync(0xffffffffu, s, off);
    if (lane == 0) swp[w] = s;
    __syncthreads();
    if (t < 8) {
        int v = swp[t];
        #pragma unroll
        for (int off = 4; off > 0; off >>= 1) v += __shfl_xor_sync(0xffu, v, off);
        if (t == 0) g_blksum[b] = v;
    }
}

// exclusive scan of 98 block sums (1 block, 128 thr)
__global__ void k_scan2() {
    __shared__ int swp[4];
    int t = threadIdx.x, lane = t & 31, w = t >> 5;
    int v = (t < NBLK) ? g_blksum[t] : 0;
    int incl = v;
    #pragma unroll
    for (int off = 1; off < 32; off <<= 1) {
        int u = __shfl_up_sync(0xffffffffu, incl, off);
        if (lane >= off) incl += u;
    }
    if (lane == 31) swp[w] = incl;
    __syncthreads();
    int basew = 0;
    for (int i = 0; i < w; i++) basew += swp[i];
    incl += basew;
    if (t < NBLK) g_blksum[t] = incl - v;
    if (t == 127) g_off[NN] = incl;
}

__global__ void k_scan3() {
    __shared__ int swp[8];
    int t = threadIdx.x, b = blockIdx.x;
    int lane = t & 31, w = t >> 5;
    int base = b * SCAN_CHUNK + t * SCAN_ITEMS;
    int d[SCAN_ITEMS]; int s = 0;
    #pragma unroll
    for (int i = 0; i < SCAN_ITEMS; i++) {
        int idx = base + i;
        d[i] = (idx < NN) ? g_deg[idx] : 0;
        s += d[i];
    }
    int incl = s;
    #pragma unroll
    for (int off = 1; off < 32; off <<= 1) {
        int u = __shfl_up_sync(0xffffffffu, incl, off);
        if (lane >= off) incl += u;
    }
    if (lane == 31) swp[w] = incl;
    __syncthreads();
    int basew = g_blksum[b];
    for (int i = 0; i < w; i++) basew += swp[i];
    int excl = basew + incl - s;
    #pragma unroll
    for (int i = 0; i < SCAN_ITEMS; i++) {
        int idx = base + i;
        if (idx < NN) {
            g_off[idx] = excl;
            g_cur[idx] = excl;
            excl += d[i];
        }
    }
}

__global__ void k_reorder(const int* __restrict__ ei, int nE) {
    int e = blockIdx.x * 256 + threadIdx.x;
    if (e >= nE) return;
    int dst = __ldg(&ei[(size_t)nE + e]);
    int pos = atomicAdd(&g_cur[dst], 1);
    g_sorted[pos] = __ldg(&ei[e]);
}

// ============================================================
// Temporal: conv1d(+ReLU) + folded 205->16 matmul.
// TWO nodes per thread: each broadcast weight LDS.128 feeds 8
// FMAs instead of 4 (halves the L1/LSU pressure that ncu showed
// as the 63% binding resource).
// ============================================================
__global__ __launch_bounds__(128) void k_temporal(const float* __restrict__ x,
                                                  const float* __restrict__ conv_w,
                                                  const float* __restrict__ conv_b,
                                                  int n) {
    __shared__ __align__(16) float sW[FLAT * HID];
    __shared__ float scw[OUT_CH * KW];
    __shared__ float scb[OUT_CH];
    __shared__ float sbf[HID];
    int tid = threadIdx.x;
    for (int i = tid; i < FLAT * HID; i += 128) sW[i] = g_Wc[i];
    if (tid < OUT_CH * KW) scw[tid] = conv_w[tid];
    if (tid < OUT_CH) scb[tid] = conv_b[tid];
    if (tid < HID) sbf[tid] = g_bfc[tid];
    __syncthreads();

    int v0 = blockIdx.x * 256 + tid;
    if (v0 >= n) return;
    int v1 = v0 + 128;
    bool has1 = (v1 < n);
    int v1c = has1 ? v1 : v0;        // clamp: duplicate work, discard store

    const float4* x40 = (const float4*)(x + (size_t)v0 * T_LEN);
    const float4* x41 = (const float4*)(x + (size_t)v1c * T_LEN);

    float acc0[HID], acc1[HID];
    #pragma unroll
    for (int j = 0; j < HID; j++) { acc0[j] = sbf[j]; acc1[j] = sbf[j]; }

    float f0[20], f1[20];
    #pragma unroll
    for (int q = 0; q < 5; q++) {
        float4 a = __ldg(&x40[q]);
        f0[q * 4] = a.x; f0[q * 4 + 1] = a.y; f0[q * 4 + 2] = a.z; f0[q * 4 + 3] = a.w;
        float4 b = __ldg(&x41[q]);
        f1[q * 4] = b.x; f1[q * 4 + 1] = b.y; f1[q * 4 + 2] = b.z; f1[q * 4 + 3] = b.w;
    }

    for (int g = 0; g < 10; g++) {
        #pragma unroll
        for (int tl = 0; tl < 4; tl++) {
            int t = g * 4 + tl;
            float cv0[OUT_CH], cv1[OUT_CH];
            #pragma unroll
            for (int c = 0; c < OUT_CH; c++) {
                float s0 = scb[c], s1 = scb[c];
                #pragma unroll
                for (int k = 0; k < KW; k++) {
                    float wk = scw[c * KW + k];
                    s0 = fmaf(wk, f0[3 * tl + k], s0);
                    s1 = fmaf(wk, f1[3 * tl + k], s1);
                }
                cv0[c] = fmaxf(s0, 0.f);
                cv1[c] = fmaxf(s1, 0.f);
            }
            #pragma unroll
            for (int c = 0; c < OUT_CH; c++) {
                const float4* wr = (const float4*)&sW[(c * L_OUT + t) * HID];
                #pragma unroll
                for (int q2 = 0; q2 < 4; q2++) {
                    float4 w = wr[q2];
                    acc0[q2 * 4 + 0] = fmaf(w.x, cv0[c], acc0[q2 * 4 + 0]);
                    acc0[q2 * 4 + 1] = fmaf(w.y, cv0[c], acc0[q2 * 4 + 1]);
                    acc0[q2 * 4 + 2] = fmaf(w.z, cv0[c], acc0[q2 * 4 + 2]);
                    acc0[q2 * 4 + 3] = fmaf(w.w, cv0[c], acc0[q2 * 4 + 3]);
                    acc1[q2 * 4 + 0] = fmaf(w.x, cv1[c], acc1[q2 * 4 + 0]);
                    acc1[q2 * 4 + 1] = fmaf(w.y, cv1[c], acc1[q2 * 4 + 1]);
                    acc1[q2 * 4 + 2] = fmaf(w.z, cv1[c], acc1[q2 * 4 + 2]);
                    acc1[q2 * 4 + 3] = fmaf(w.w, cv1[c], acc1[q2 * 4 + 3]);
                }
            }
        }
        if (g != 9) {
            #pragma unroll
            for (int i = 0; i < 8; i++) { f0[i] = f0[i + 12]; f1[i] = f1[i + 12]; }
            #pragma unroll
            for (int q = 0; q < 3; q++) {
                float4 a = __ldg(&x40[3 * g + 5 + q]);
                f0[8 + q * 4] = a.x; f0[9 + q * 4] = a.y; f0[10 + q * 4] = a.z; f0[11 + q * 4] = a.w;
                float4 b = __ldg(&x41[3 * g + 5 + q]);
                f1[8 + q * 4] = b.x; f1[9 + q * 4] = b.y; f1[10 + q * 4] = b.z; f1[11 + q * 4] = b.w;
            }
        }
    }
    { // tail t=40, window f[12..18]
        float cv0[OUT_CH], cv1[OUT_CH];
        #pragma unroll
        for (int c = 0; c < OUT_CH; c++) {
            float s0 = scb[c], s1 = scb[c];
            #pragma unroll
            for (int k = 0; k < KW; k++) {
                float wk = scw[c * KW + k];
                s0 = fmaf(wk, f0[12 + k], s0);
                s1 = fmaf(wk, f1[12 + k], s1);
            }
            cv0[c] = fmaxf(s0, 0.f);
            cv1[c] = fmaxf(s1, 0.f);
        }
        #pragma unroll
        for (int c = 0; c < OUT_CH; c++) {
            const float4* wr = (const float4*)&sW[(c * L_OUT + 40) * HID];
            #pragma unroll
            for (int q2 = 0; q2 < 4; q2++) {
                float4 w = wr[q2];
                acc0[q2 * 4 + 0] = fmaf(w.x, cv0[c], acc0[q2 * 4 + 0]);
                acc0[q2 * 4 + 1] = fmaf(w.y, cv0[c], acc0[q2 * 4 + 1]);
                acc0[q2 * 4 + 2] = fmaf(w.z, cv0[c], acc0[q2 * 4 + 2]);
                acc0[q2 * 4 + 3] = fmaf(w.w, cv0[c], acc0[q2 * 4 + 3]);
                acc1[q2 * 4 + 0] = fmaf(w.x, cv1[c], acc1[q2 * 4 + 0]);
                acc1[q2 * 4 + 1] = fmaf(w.y, cv1[c], acc1[q2 * 4 + 1]);
                acc1[q2 * 4 + 2] = fmaf(w.z, cv1[c], acc1[q2 * 4 + 2]);
                acc1[q2 * 4 + 3] = fmaf(w.w, cv1[c], acc1[q2 * 4 + 3]);
            }
        }
    }

    float4* p10 = (float4*)&g_p1[(size_t)v0 * HID];
    #pragma unroll
    for (int q = 0; q < 4; q++)
        p10[q] = make_float4(acc0[q * 4], acc0[q * 4 + 1], acc0[q * 4 + 2], acc0[q * 4 + 3]);
    if (has1) {
        float4* p11 = (float4*)&g_p1[(size_t)v1 * HID];
        #pragma unroll
        for (int q = 0; q < 4; q++)
            p11[q] = make_float4(acc1[q * 4], acc1[q * 4 + 1], acc1[q * 4 + 2], acc1[q * 4 + 3]);
    }
}

// ============================================================
// CSR aggregation: warp per node, 4 lanes per edge (one float4
// quarter each), register accumulate + 12-shfl reduction.
// ============================================================
__global__ __launch_bounds__(256) void k_agg_csr(int layer) {
    const float* __restrict__ p = layer ? g_p2 : g_p1;
    float* __restrict__ agg = layer ? g_agg2 : g_agg1;
    int lane = threadIdx.x & 31;
    int v = blockIdx.x * 8 + (threadIdx.x >> 5);
    if (v >= NN) return;
    int start = __ldg(&g_off[v]);
    int end   = __ldg(&g_off[v + 1]);
    int q  = lane & 3;
    int es = lane >> 2;
    float4 acc = make_float4(0.f, 0.f, 0.f, 0.f);
    for (int e0 = start; e0 < end; e0 += 8) {
        int e = e0 + es;
        if (e < end) {
            int s = __ldg(&g_sorted[e]);
            float4 t = __ldg(&((const float4*)(p + (size_t)s * HID))[q]);
            acc.x += t.x; acc.y += t.y; acc.z += t.z; acc.w += t.w;
        }
    }
    #pragma unroll
    for (int off = 4; off < 32; off <<= 1) {
        acc.x += __shfl_xor_sync(0xffffffffu, acc.x, off);
        acc.y += __shfl_xor_sync(0xffffffffu, acc.y, off);
        acc.z += __shfl_xor_sync(0xffffffffu, acc.z, off);
        acc.w += __shfl_xor_sync(0xffffffffu, acc.w, off);
    }
    if (lane < 4) ((float4*)(agg + (size_t)v * HID))[lane] = acc;
}

// ============================================================
// GIN1 node update
// ============================================================
__global__ __launch_bounds__(256) void k_gin1(const float* __restrict__ g1b1,
                                              const float* __restrict__ g1w2,
                                              const float* __restrict__ g1b2,
                                              const float* __restrict__ g2w1, int n) {
    __shared__ float sw2[HID * HID], sw3[HID * HID], sb1[HID], sb2[HID];
    int tid = threadIdx.x;
    if (tid < HID * HID) { sw2[tid] = g1w2[tid]; sw3[tid] = g2w1[tid]; }
    if (tid < HID) { sb1[tid] = g1b1[tid]; sb2[tid] = g1b2[tid]; }
    __syncthreads();
    int v = blockIdx.x * 256 + tid;
    if (v >= n) return;

    const float4* p1 = (const float4*)&g_p1[(size_t)v * HID];
    const float4* a1 = (const float4*)&g_agg1[(size_t)v * HID];
    float q[HID];
    #pragma unroll
    for (int i = 0; i < 4; i++) {
        float4 pv = p1[i], av = a1[i];
        q[i * 4 + 0] = fmaxf(pv.x + av.x + sb1[i * 4 + 0], 0.f);
        q[i * 4 + 1] = fmaxf(pv.y + av.y + sb1[i * 4 + 1], 0.f);
        q[i * 4 + 2] = fmaxf(pv.z + av.z + sb1[i * 4 + 2], 0.f);
        q[i * 4 + 3] = fmaxf(pv.w + av.w + sb1[i * 4 + 3], 0.f);
    }
    float h2[HID];
    #pragma unroll
    for (int k = 0; k < HID; k++) {
        float s = sb2[k];
        #pragma unroll
        for (int j = 0; j < HID; j++) s = fmaf(q[j], sw2[k * HID + j], s);
        h2[k] = fmaxf(s, 0.f);
    }
    float4* p2 = (float4*)&g_p2[(size_t)v * HID];
    #pragma unroll
    for (int i = 0; i < 4; i++) {
        float o[4];
        #pragma unroll
        for (int u = 0; u < 4; u++) {
            int j = i * 4 + u;
            float s = 0.f;
            #pragma unroll
            for (int k = 0; k < HID; k++) s = fmaf(h2[k], sw3[j * HID + k], s);
            o[u] = s;
        }
        p2[i] = make_float4(o[0], o[1], o[2], o[3]);
    }
}

// ============================================================
// Output
// ============================================================
__global__ __launch_bounds__(256) void k_out(const float* __restrict__ g2b1,
                                             float* __restrict__ out, int n) {
    __shared__ float sw[HID], sb[HID];
    int tid = threadIdx.x;
    if (tid < HID) { sw[tid] = g_wout[tid]; sb[tid] = g2b1[tid]; }
    __syncthreads();
    int v = blockIdx.x * 256 + tid;
    if (v >= n) return;
    const float4* p2 = (const float4*)&g_p2[(size_t)v * HID];
    const float4* a2 = (const float4*)&g_agg2[(size_t)v * HID];
    float s = g_bout;
    #pragma unroll
    for (int i = 0; i < 4; i++) {
        float4 pv = p2[i], av = a2[i];
        s = fmaf(fmaxf(pv.x + av.x + sb[i * 4 + 0], 0.f), sw[i * 4 + 0], s);
        s = fmaf(fmaxf(pv.y + av.y + sb[i * 4 + 1], 0.f), sw[i * 4 + 1], s);
        s = fmaf(fmaxf(pv.z + av.z + sb[i * 4 + 2], 0.f), sw[i * 4 + 2], s);
        s = fmaf(fmaxf(pv.w + av.w + sb[i * 4 + 3], 0.f), sw[i * 4 + 3], s);
    }
    out[v] = s;
}

extern "C" void kernel_launch(void* const* d_in, const int* in_sizes, int n_in,
                              void* d_out, int out_size) {
    const float* x       = (const float*)d_in[0];
    const int*   ei      = (const int*)d_in[1];      // int32 (JAX x64 off)
    const float* conv_w  = (const float*)d_in[2];
    const float* conv_b  = (const float*)d_in[3];
    const float* fc_w    = (const float*)d_in[4];
    const float* fc_b    = (const float*)d_in[5];
    const float* g1w1    = (const float*)d_in[6];
    const float* g1b1    = (const float*)d_in[7];
    const float* g1w2    = (const float*)d_in[8];
    const float* g1b2    = (const float*)d_in[9];
    const float* g2w1    = (const float*)d_in[10];
    const float* g2b1    = (const float*)d_in[11];
    const float* g2w2    = (const float*)d_in[12];
    const float* g2b2    = (const float*)d_in[13];
    const float* ro_w    = (const float*)d_in[14];
    const float* ro_b    = (const float*)d_in[15];
    float* out = (float*)d_out;

    int n  = in_sizes[0] / T_LEN;   // 100000
    int nE = in_sizes[1] / 2;       // 3200000

    // k_temporal at launch index 3 so ncu profiles it (verify the LDS-halving).
    k_setup<<<1, 256>>>(fc_w, fc_b, g1w1, g2w2, g2b2, ro_w, ro_b);
    k_zero<<<(NN + 255) / 256, 256>>>();
    k_hist<<<(nE + 255) / 256, 256>>>(ei, nE);
    k_temporal<<<(n + 255) / 256, 128>>>(x, conv_w, conv_b, n);
    k_scan1<<<NBLK, SCAN_BLK>>>();
    k_scan2<<<1, 128>>>();
    k_scan3<<<NBLK, SCAN_BLK>>>();
    k_reorder<<<(nE + 255) / 256, 256>>>(ei, nE);
    k_agg_csr<<<(NN + 7) / 8, 256>>>(0);
    k_gin1<<<(n + 255) / 256, 256>>>(g1b1, g1w2, g1b2, g2w1, n);
    k_agg_csr<<<(NN + 7) / 8, 256>>>(1);
    k_out<<<(n + 255) / 256, 256>>>(g2b1, out, n);
}